// round 2
// baseline (speedup 1.0000x reference)
#include <cuda_runtime.h>
#include <math.h>

// Problem constants (fixed by setup_inputs)
#define B_      16
#define T_      1033
#define C_      768
#define H_      12
#define HD_     64
#define OFFSET_ 9
#define BT_     (B_ * T_)          // 16528 rows

// Scratch (static device globals — allocation-free per harness rules)
__device__ float g_q[(size_t)BT_ * C_];
__device__ float g_k[(size_t)BT_ * C_];
__device__ float g_v[(size_t)BT_ * C_];
__device__ float g_y[(size_t)BT_ * C_];

// ============================================================
// SGEMM (NT): C[m,n] = sum_k A[m,k] * B[n,k]
//   A: [M,K] row-major, B: [N,K] row-major  (both K-contiguous)
// Classic 128x128 block, BK=8, 8x8 per-thread microtile, 256 threads.
// ============================================================
#define BM 128
#define BN 128
#define BKg 8
#define TMt 8
#define TNt 8

__global__ __launch_bounds__(256)
void sgemm_nt(const float* __restrict__ A, const float* __restrict__ Bm,
              float* __restrict__ Cm, int M, int N, int K)
{
    __shared__ float As[BKg][BM];
    __shared__ float Bs[BKg][BN];

    const int bm  = blockIdx.y * BM;
    const int bn  = blockIdx.x * BN;
    const int tid = threadIdx.x;

    // Tile load mapping: 1024 floats per tile = 256 x float4
    const int lr = tid >> 1;          // 0..127 (row within tile)
    const int lc = (tid & 1) << 2;    // 0 or 4 (k offset)

    // Compute mapping: 16x16 thread grid of 8x8 microtiles
    const int trow = (tid >> 4) << 3; // 0..120
    const int tcol = (tid & 15) << 3; // 0..120

    float acc[TMt][TNt];
    #pragma unroll
    for (int i = 0; i < TMt; i++)
        #pragma unroll
        for (int j = 0; j < TNt; j++)
            acc[i][j] = 0.f;

    for (int k0 = 0; k0 < K; k0 += BKg) {
        // Load A tile (guard M edge), store transposed
        const int gm = bm + lr;
        float4 a4 = make_float4(0.f, 0.f, 0.f, 0.f);
        if (gm < M)
            a4 = *reinterpret_cast<const float4*>(A + (size_t)gm * K + k0 + lc);
        As[lc + 0][lr] = a4.x;
        As[lc + 1][lr] = a4.y;
        As[lc + 2][lr] = a4.z;
        As[lc + 3][lr] = a4.w;

        // Load B tile (N always a multiple of 128 here)
        const int gn = bn + lr;
        float4 b4 = *reinterpret_cast<const float4*>(Bm + (size_t)gn * K + k0 + lc);
        Bs[lc + 0][lr] = b4.x;
        Bs[lc + 1][lr] = b4.y;
        Bs[lc + 2][lr] = b4.z;
        Bs[lc + 3][lr] = b4.w;

        __syncthreads();

        #pragma unroll
        for (int kk = 0; kk < BKg; kk++) {
            float ar[TMt], br[TNt];
            #pragma unroll
            for (int i = 0; i < TMt; i++) ar[i] = As[kk][trow + i];
            #pragma unroll
            for (int j = 0; j < TNt; j++) br[j] = Bs[kk][tcol + j];
            #pragma unroll
            for (int i = 0; i < TMt; i++)
                #pragma unroll
                for (int j = 0; j < TNt; j++)
                    acc[i][j] += ar[i] * br[j];
        }
        __syncthreads();
    }

    // Store (guard M edge), vectorized
    #pragma unroll
    for (int i = 0; i < TMt; i++) {
        const int gm = bm + trow + i;
        if (gm < M) {
            float* cp = Cm + (size_t)gm * N + bn + tcol;
            float4 v0 = make_float4(acc[i][0], acc[i][1], acc[i][2], acc[i][3]);
            float4 v1 = make_float4(acc[i][4], acc[i][5], acc[i][6], acc[i][7]);
            *reinterpret_cast<float4*>(cp)     = v0;
            *reinterpret_cast<float4*>(cp + 4) = v1;
        }
    }
}

// ============================================================
// Fused LayerNorm (over C=768) + axial RoPE (per head, pairs)
// One block per row, 256 threads. In-place.
// ============================================================
__global__ __launch_bounds__(256)
void ln_rope_kernel(float* __restrict__ buf,
                    const float* __restrict__ w, const float* __restrict__ bvec,
                    const float* __restrict__ fcos, const float* __restrict__ fsin)
{
    const int row = blockIdx.x;        // 0..BT_-1
    const int tid = threadIdx.x;       // 256
    float* in = buf + (size_t)row * C_;

    __shared__ float s_row[C_];
    float sum = 0.f, sq = 0.f;
    #pragma unroll
    for (int i = tid; i < C_; i += 256) {
        float v = in[i];
        s_row[i] = v;
        sum += v;
        sq  += v * v;
    }
    // block reduce (8 warps)
    #pragma unroll
    for (int o = 16; o > 0; o >>= 1) {
        sum += __shfl_xor_sync(0xffffffffu, sum, o);
        sq  += __shfl_xor_sync(0xffffffffu, sq,  o);
    }
    __shared__ float ws[8], wq[8];
    __shared__ float s_mean, s_rstd;
    const int warp = tid >> 5, lane = tid & 31;
    if (lane == 0) { ws[warp] = sum; wq[warp] = sq; }
    __syncthreads();
    if (tid == 0) {
        float S = 0.f, Q = 0.f;
        #pragma unroll
        for (int i = 0; i < 8; i++) { S += ws[i]; Q += wq[i]; }
        float m   = S / (float)C_;
        float var = Q / (float)C_ - m * m;
        s_mean = m;
        s_rstd = rsqrtf(var + 1e-5f);
    }
    __syncthreads();

    const float m = s_mean, r = s_rstd;
    const int t = row % T_;
    const bool rope = (t >= OFFSET_);
    const int p = t - OFFSET_;

    // 384 pairs per row
    for (int pr = tid; pr < (C_ / 2); pr += 256) {
        const int c0 = pr << 1, c1 = c0 + 1;
        float e = (s_row[c0] - m) * r * w[c0] + bvec[c0];
        float o = (s_row[c1] - m) * r * w[c1] + bvec[c1];
        if (rope) {
            const int i = pr & 31;            // pair index within head (hd/2 = 32)
            const float cv = fcos[p * 32 + i];
            const float sv = fsin[p * 32 + i];
            const float ne = e * cv - o * sv;
            const float no = e * sv + o * cv;
            e = ne; o = no;
        }
        in[c0] = e;
        in[c1] = o;
    }
}

// ============================================================
// Flash attention (non-causal, full softmax over T keys)
// One (b,h) per blockIdx.y, 128 queries per CTA (1 query/thread).
// K/V tiles of 64 keys staged in smem; online softmax one-pass.
// exp folded into exp2 via scale*log2e pre-applied to q regs.
// ============================================================
#define TQf 128
#define TKf 64
#define QSCALE 0.180336884f   // (1/sqrt(64)) * log2(e)

__global__ __launch_bounds__(128)
void flash_kernel(const float* __restrict__ Qb, const float* __restrict__ Kb,
                  const float* __restrict__ Vb, float* __restrict__ Yb)
{
    __shared__ float sbuf[TQf * HD_];   // 32KB; reused: Q stage -> (Ks,Vs) -> O stage
    float (*Ks)[HD_] = reinterpret_cast<float (*)[HD_]>(sbuf);
    float (*Vs)[HD_] = reinterpret_cast<float (*)[HD_]>(sbuf + TKf * HD_);

    const int qb  = blockIdx.x * TQf;
    const int bh  = blockIdx.y;
    const int b   = bh / H_;
    const int h   = bh % H_;
    const int tid = threadIdx.x;

    const size_t rowbase = (size_t)b * T_;
    const int hoff = h * HD_;

    // Stage Q tile coalesced into smem
    for (int idx = tid; idx < TQf * HD_; idx += 128) {
        const int r = idx >> 6, d = idx & 63;
        sbuf[idx] = (qb + r < T_) ? Qb[(rowbase + qb + r) * C_ + hoff + d] : 0.f;
    }
    __syncthreads();

    float q[HD_], o[HD_];
    #pragma unroll
    for (int d = 0; d < HD_; d++) {
        q[d] = sbuf[tid * HD_ + d] * QSCALE;
        o[d] = 0.f;
    }
    float mmax = -1e30f, lsum = 0.f;
    const bool active = (qb + tid) < T_;
    __syncthreads();

    for (int kb = 0; kb < T_; kb += TKf) {
        const int nk = (T_ - kb < TKf) ? (T_ - kb) : TKf;
        // Load K and V tiles (coalesced)
        for (int idx = tid; idx < TKf * HD_; idx += 128) {
            const int r = idx >> 6, d = idx & 63;
            if (r < nk) {
                const size_t g = (rowbase + kb + r) * C_ + hoff + d;
                Ks[r][d] = Kb[g];
                Vs[r][d] = Vb[g];
            }
        }
        __syncthreads();

        if (active) {
            for (int j = 0; j < nk; j++) {
                float s = 0.f;
                #pragma unroll
                for (int d = 0; d < HD_; d++) s += q[d] * Ks[j][d];
                if (s > mmax) {
                    const float corr = exp2f(mmax - s);
                    lsum *= corr;
                    #pragma unroll
                    for (int d = 0; d < HD_; d++) o[d] *= corr;
                    mmax = s;
                }
                const float pw = exp2f(s - mmax);
                lsum += pw;
                #pragma unroll
                for (int d = 0; d < HD_; d++) o[d] += pw * Vs[j][d];
            }
        }
        __syncthreads();
    }

    // Stage O through smem for coalesced store
    if (active) {
        const float inv = 1.0f / lsum;
        #pragma unroll
        for (int d = 0; d < HD_; d++) sbuf[tid * HD_ + d] = o[d] * inv;
    }
    __syncthreads();
    for (int idx = tid; idx < TQf * HD_; idx += 128) {
        const int r = idx >> 6, d = idx & 63;
        if (qb + r < T_)
            Yb[(rowbase + qb + r) * C_ + hoff + d] = sbuf[idx];
    }
}

// ============================================================
// Host launcher
// ============================================================
extern "C" void kernel_launch(void* const* d_in, const int* in_sizes, int n_in,
                              void* d_out, int out_size)
{
    const float* x    = (const float*)d_in[0];
    const float* Wq   = (const float*)d_in[1];
    const float* Wk   = (const float*)d_in[2];
    const float* Wv   = (const float*)d_in[3];
    const float* Wp   = (const float*)d_in[4];
    const float* qn_w = (const float*)d_in[5];
    const float* qn_b = (const float*)d_in[6];
    const float* kn_w = (const float*)d_in[7];
    const float* kn_b = (const float*)d_in[8];
    const float* fcos = (const float*)d_in[9];
    const float* fsin = (const float*)d_in[10];
    float* out = (float*)d_out;

    float *q, *k, *v, *y;
    cudaGetSymbolAddress((void**)&q, g_q);
    cudaGetSymbolAddress((void**)&k, g_k);
    cudaGetSymbolAddress((void**)&v, g_v);
    cudaGetSymbolAddress((void**)&y, g_y);

    const dim3 ggrid(C_ / BN, (BT_ + BM - 1) / BM);   // (6, 130)

    sgemm_nt<<<ggrid, 256>>>(x, Wq, q, BT_, C_, C_);
    sgemm_nt<<<ggrid, 256>>>(x, Wk, k, BT_, C_, C_);
    sgemm_nt<<<ggrid, 256>>>(x, Wv, v, BT_, C_, C_);

    ln_rope_kernel<<<BT_, 256>>>(q, qn_w, qn_b, fcos, fsin);
    ln_rope_kernel<<<BT_, 256>>>(k, kn_w, kn_b, fcos, fsin);

    const dim3 fgrid((T_ + TQf - 1) / TQf, B_ * H_);  // (9, 192)
    flash_kernel<<<fgrid, 128>>>(q, k, v, y);

    sgemm_nt<<<ggrid, 256>>>(y, Wp, out, BT_, C_, C_);
}

// round 4
// speedup vs baseline: 6.7050x; 6.7050x over previous
#include <cuda_runtime.h>
#include <cuda_fp16.h>
#include <stdint.h>
#include <math.h>

// Problem constants
#define B_      16
#define T_      1033
#define C_      768
#define H_      12
#define HD_     64
#define OFFSET_ 9
#define BT_     (B_ * T_)          // 16528 rows
#define QSCALE  0.180336884f       // (1/sqrt(64)) * log2(e)

// ---------------- scratch (static device globals) ----------------
__device__ float  g_q [(size_t)BT_ * C_];
__device__ float  g_k [(size_t)BT_ * C_];
__device__ __half g_qh[(size_t)BT_ * C_];
__device__ __half g_kh[(size_t)BT_ * C_];
__device__ __half g_vh[(size_t)BT_ * C_];
__device__ __half g_yh[(size_t)BT_ * C_];
__device__ __half g_xh[(size_t)BT_ * C_];
__device__ __half g_wqh[(size_t)C_ * C_];
__device__ __half g_wkh[(size_t)C_ * C_];
__device__ __half g_wvh[(size_t)C_ * C_];
__device__ __half g_wph[(size_t)C_ * C_];

// ---------------- PTX helpers (arch-agnostic: mma.sync + ldmatrix) ----------------
__device__ __forceinline__ uint32_t smem_u32(const void* p) {
    uint32_t a;
    asm("{ .reg .u64 t; cvta.to.shared.u64 t, %1; cvt.u32.u64 %0, t; }" : "=r"(a) : "l"(p));
    return a;
}
__device__ __forceinline__ void ldsm_x4(uint32_t* r, uint32_t addr) {
    asm volatile("ldmatrix.sync.aligned.m8n8.x4.shared.b16 {%0,%1,%2,%3}, [%4];"
                 : "=r"(r[0]), "=r"(r[1]), "=r"(r[2]), "=r"(r[3]) : "r"(addr));
}
__device__ __forceinline__ void ldsm_x4_t(uint32_t* r, uint32_t addr) {
    asm volatile("ldmatrix.sync.aligned.m8n8.x4.trans.shared.b16 {%0,%1,%2,%3}, [%4];"
                 : "=r"(r[0]), "=r"(r[1]), "=r"(r[2]), "=r"(r[3]) : "r"(addr));
}
__device__ __forceinline__ void mma16816(float* c, const uint32_t* a, uint32_t b0, uint32_t b1) {
    asm volatile("mma.sync.aligned.m16n8k16.row.col.f32.f16.f16.f32 "
                 "{%0,%1,%2,%3}, {%4,%5,%6,%7}, {%8,%9}, {%0,%1,%2,%3};"
                 : "+f"(c[0]), "+f"(c[1]), "+f"(c[2]), "+f"(c[3])
                 : "r"(a[0]), "r"(a[1]), "r"(a[2]), "r"(a[3]), "r"(b0), "r"(b1));
}
__device__ __forceinline__ float ex2(float x) {
    float y;
    asm("ex2.approx.ftz.f32 %0, %1;" : "=f"(y) : "f"(x));
    return y;
}
__device__ __forceinline__ uint32_t packh2(float a, float b) {
    __half2 h = __floats2half2_rn(a, b);
    return *reinterpret_cast<uint32_t*>(&h);
}
__device__ __forceinline__ void store2(float* p, float a, float b) {
    *reinterpret_cast<float2*>(p) = make_float2(a, b);
}
__device__ __forceinline__ void store2(__half* p, float a, float b) {
    *reinterpret_cast<__half2*>(p) = __floats2half2_rn(a, b);
}

// ============================================================
// fp32 -> fp16 conversion
// ============================================================
__global__ __launch_bounds__(256)
void f2h_kernel(const float* __restrict__ in, __half* __restrict__ out, int n4)
{
    int i = blockIdx.x * blockDim.x + threadIdx.x;
    if (i < n4) {
        float4 v = reinterpret_cast<const float4*>(in)[i];
        uint2 pk;
        pk.x = packh2(v.x, v.y);
        pk.y = packh2(v.z, v.w);
        reinterpret_cast<uint2*>(out)[i] = pk;
    }
}

// ============================================================
// HGEMM (NT) via mma.sync: C[m,n] = sum_k A[m,k]*W[n,k]
// A: [M,768] fp16 row-major, W: [768,768] fp16 row-major, C: [M,768] OutT
// CTA 128x128, BK=32, 8 warps of 64x32.
// ============================================================
template<typename OutT>
__global__ __launch_bounds__(256)
void hgemm_mma(const __half* __restrict__ A, const __half* __restrict__ Bw,
               OutT* __restrict__ Cm, int M)
{
    __shared__ __half As[128][40];
    __shared__ __half Bs[128][40];

    const int tid  = threadIdx.x;
    const int lane = tid & 31, wid = tid >> 5;
    const int wm   = (wid >> 2) * 64;       // 0 or 64
    const int wn   = (wid & 3) * 32;        // 0..96
    const int bm   = blockIdx.y * 128, bn = blockIdx.x * 128;

    const int gg = lane >> 3, lr = lane & 7;

    float acc[4][4][4];
    #pragma unroll
    for (int i = 0; i < 4; i++)
        #pragma unroll
        for (int j = 0; j < 4; j++)
            #pragma unroll
            for (int r = 0; r < 4; r++) acc[i][j][r] = 0.f;

    const uint32_t aBase = smem_u32(&As[0][0]);
    const uint32_t bBase = smem_u32(&Bs[0][0]);

    for (int kt = 0; kt < C_ / 32; kt++) {
        #pragma unroll
        for (int i = 0; i < 2; i++) {
            const int c = tid + i * 256;     // 0..511
            const int r = c >> 2, cb = (c & 3) * 8;
            uint4 av = make_uint4(0u, 0u, 0u, 0u);
            if (bm + r < M)
                av = *reinterpret_cast<const uint4*>(A + (size_t)(bm + r) * C_ + kt * 32 + cb);
            *reinterpret_cast<uint4*>(&As[r][cb]) = av;
            uint4 bv = *reinterpret_cast<const uint4*>(Bw + (size_t)(bn + r) * C_ + kt * 32 + cb);
            *reinterpret_cast<uint4*>(&Bs[r][cb]) = bv;
        }
        __syncthreads();

        #pragma unroll
        for (int ks = 0; ks < 32; ks += 16) {
            uint32_t af[4][4], bf[4][2];
            #pragma unroll
            for (int i = 0; i < 4; i++) {
                const uint32_t addr = aBase +
                    ((wm + i * 16 + (gg & 1) * 8 + lr) * 40 + ks + (gg >> 1) * 8) * 2;
                ldsm_x4(af[i], addr);
            }
            #pragma unroll
            for (int np = 0; np < 2; np++) {
                uint32_t r4[4];
                const uint32_t addr = bBase +
                    ((wn + np * 16 + (gg >> 1) * 8 + lr) * 40 + ks + (gg & 1) * 8) * 2;
                ldsm_x4(r4, addr);
                bf[2 * np][0]     = r4[0]; bf[2 * np][1]     = r4[1];
                bf[2 * np + 1][0] = r4[2]; bf[2 * np + 1][1] = r4[3];
            }
            #pragma unroll
            for (int i = 0; i < 4; i++)
                #pragma unroll
                for (int j = 0; j < 4; j++)
                    mma16816(acc[i][j], af[i], bf[j][0], bf[j][1]);
        }
        __syncthreads();
    }

    // epilogue: c0,c1 = (row, col..col+1); c2,c3 = (row+8, ...)
    #pragma unroll
    for (int i = 0; i < 4; i++) {
        const int row0 = bm + wm + i * 16 + (lane >> 2);
        #pragma unroll
        for (int j = 0; j < 4; j++) {
            const int col = bn + wn + j * 8 + (lane & 3) * 2;
            if (row0 < M)     store2(Cm + (size_t)row0 * C_ + col,       acc[i][j][0], acc[i][j][1]);
            if (row0 + 8 < M) store2(Cm + (size_t)(row0 + 8) * C_ + col, acc[i][j][2], acc[i][j][3]);
        }
    }
}

// ============================================================
// Fused LayerNorm + axial RoPE; fp32 in -> scaled fp16 out
// ============================================================
__global__ __launch_bounds__(256)
void ln_rope_h(const float* __restrict__ buf, __half* __restrict__ outh,
               const float* __restrict__ w, const float* __restrict__ bvec,
               const float* __restrict__ fcos, const float* __restrict__ fsin,
               float oscale)
{
    const int row = blockIdx.x;
    const int tid = threadIdx.x;
    const float* in = buf + (size_t)row * C_;

    __shared__ float s_row[C_];
    float sum = 0.f, sq = 0.f;
    #pragma unroll
    for (int i = tid; i < C_; i += 256) {
        float v = in[i];
        s_row[i] = v;
        sum += v;
        sq  += v * v;
    }
    #pragma unroll
    for (int o = 16; o > 0; o >>= 1) {
        sum += __shfl_xor_sync(0xffffffffu, sum, o);
        sq  += __shfl_xor_sync(0xffffffffu, sq,  o);
    }
    __shared__ float ws[8], wq[8];
    __shared__ float s_mean, s_rstd;
    const int warp = tid >> 5, lane = tid & 31;
    if (lane == 0) { ws[warp] = sum; wq[warp] = sq; }
    __syncthreads();
    if (tid == 0) {
        float S = 0.f, Q = 0.f;
        #pragma unroll
        for (int i = 0; i < 8; i++) { S += ws[i]; Q += wq[i]; }
        float mn  = S / (float)C_;
        float var = Q / (float)C_ - mn * mn;
        s_mean = mn;
        s_rstd = rsqrtf(var + 1e-5f);
    }
    __syncthreads();

    const float mn = s_mean, rs = s_rstd;
    const int t = row % T_;
    const bool rope = (t >= OFFSET_);
    const int p = t - OFFSET_;

    for (int pr = tid; pr < (C_ / 2); pr += 256) {
        const int c0 = pr << 1, c1 = c0 + 1;
        float e = (s_row[c0] - mn) * rs * w[c0] + bvec[c0];
        float o = (s_row[c1] - mn) * rs * w[c1] + bvec[c1];
        if (rope) {
            const int i = pr & 31;
            const float cv = fcos[p * 32 + i];
            const float sv = fsin[p * 32 + i];
            const float ne = e * cv - o * sv;
            const float no = e * sv + o * cv;
            e = ne; o = no;
        }
        *reinterpret_cast<__half2*>(outh + (size_t)row * C_ + c0) =
            __floats2half2_rn(e * oscale, o * oscale);
    }
}

// ============================================================
// Flash attention via mma.sync (FA2-style)
// CTA: 64 queries, 4 warps (16 rows each), key tiles of 64.
// ============================================================
__global__ __launch_bounds__(128)
void flash_mma(const __half* __restrict__ Qh, const __half* __restrict__ Kh,
               const __half* __restrict__ Vh, __half* __restrict__ Yh)
{
    __shared__ __half Qs[64][72];
    __shared__ __half Ks[64][72];
    __shared__ __half Vs[64][72];

    const int tid  = threadIdx.x, lane = tid & 31, wid = tid >> 5;
    const int qb   = blockIdx.x * 64;
    const int bh   = blockIdx.y;
    const int b    = bh / H_, h = bh % H_;
    const size_t base = (size_t)b * T_ * C_ + h * HD_;
    const __half* Qg = Qh + base;
    const __half* Kg = Kh + base;
    const __half* Vg = Vh + base;
    __half*       Yg = Yh + base;

    // stage Q tile
    #pragma unroll
    for (int i = 0; i < 4; i++) {
        const int c = tid + i * 128;
        const int r = c >> 3, cb = (c & 7) * 8;
        uint4 v = make_uint4(0u, 0u, 0u, 0u);
        if (qb + r < T_)
            v = *reinterpret_cast<const uint4*>(Qg + (size_t)(qb + r) * C_ + cb);
        *reinterpret_cast<uint4*>(&Qs[r][cb]) = v;
    }
    __syncthreads();

    const int gg = lane >> 3, lr = lane & 7;
    const uint32_t qBase = smem_u32(&Qs[0][0]);
    const uint32_t kBase = smem_u32(&Ks[0][0]);
    const uint32_t vBase = smem_u32(&Vs[0][0]);

    // Q fragments (warp owns rows wid*16 .. wid*16+15)
    uint32_t qf[4][4];
    const int mbase = wid * 16;
    #pragma unroll
    for (int kt = 0; kt < 4; kt++) {
        const uint32_t addr = qBase +
            ((mbase + (gg & 1) * 8 + lr) * 72 + kt * 16 + (gg >> 1) * 8) * 2;
        ldsm_x4(qf[kt], addr);
    }

    float m[2] = { -1e30f, -1e30f };
    float l[2] = { 0.f, 0.f };
    float o[8][4];
    #pragma unroll
    for (int nt = 0; nt < 8; nt++)
        #pragma unroll
        for (int r = 0; r < 4; r++) o[nt][r] = 0.f;

    const int nKT = (T_ + 63) / 64;   // 17
    for (int kbi = 0; kbi < nKT; kbi++) {
        const int kb = kbi * 64;
        __syncthreads();   // protect Ks/Vs from previous iteration's readers
        #pragma unroll
        for (int i = 0; i < 4; i++) {
            const int c = tid + i * 128;
            const int r = c >> 3, cb = (c & 7) * 8;
            uint4 kv = make_uint4(0u, 0u, 0u, 0u);
            uint4 vv = make_uint4(0u, 0u, 0u, 0u);
            if (kb + r < T_) {
                kv = *reinterpret_cast<const uint4*>(Kg + (size_t)(kb + r) * C_ + cb);
                vv = *reinterpret_cast<const uint4*>(Vg + (size_t)(kb + r) * C_ + cb);
            }
            *reinterpret_cast<uint4*>(&Ks[r][cb]) = kv;
            *reinterpret_cast<uint4*>(&Vs[r][cb]) = vv;
        }
        __syncthreads();

        // S = Q K^T  (8 n-tiles of 8 keys)
        float s[8][4];
        #pragma unroll
        for (int nt = 0; nt < 8; nt++)
            #pragma unroll
            for (int r = 0; r < 4; r++) s[nt][r] = 0.f;

        #pragma unroll
        for (int np = 0; np < 4; np++) {
            #pragma unroll
            for (int kt = 0; kt < 4; kt++) {
                uint32_t r4[4];
                const uint32_t addr = kBase +
                    ((np * 16 + (gg >> 1) * 8 + lr) * 72 + kt * 16 + (gg & 1) * 8) * 2;
                ldsm_x4(r4, addr);
                mma16816(s[2 * np],     qf[kt], r4[0], r4[1]);
                mma16816(s[2 * np + 1], qf[kt], r4[2], r4[3]);
            }
        }

        // mask out-of-range keys (last tile only)
        if (kb + 64 > T_) {
            #pragma unroll
            for (int nt = 0; nt < 8; nt++) {
                const int c0 = kb + nt * 8 + (lane & 3) * 2;
                if (c0 >= T_)     { s[nt][0] = -1e30f; s[nt][2] = -1e30f; }
                if (c0 + 1 >= T_) { s[nt][1] = -1e30f; s[nt][3] = -1e30f; }
            }
        }

        // online softmax (rows r0 = lane/4, r1 = r0+8)
        float mx0 = -1e30f, mx1 = -1e30f;
        #pragma unroll
        for (int nt = 0; nt < 8; nt++) {
            mx0 = fmaxf(mx0, fmaxf(s[nt][0], s[nt][1]));
            mx1 = fmaxf(mx1, fmaxf(s[nt][2], s[nt][3]));
        }
        mx0 = fmaxf(mx0, __shfl_xor_sync(0xffffffffu, mx0, 1));
        mx0 = fmaxf(mx0, __shfl_xor_sync(0xffffffffu, mx0, 2));
        mx1 = fmaxf(mx1, __shfl_xor_sync(0xffffffffu, mx1, 1));
        mx1 = fmaxf(mx1, __shfl_xor_sync(0xffffffffu, mx1, 2));

        const float mn0 = fmaxf(m[0], mx0);
        const float mn1 = fmaxf(m[1], mx1);
        const float a0 = ex2(m[0] - mn0);
        const float a1 = ex2(m[1] - mn1);
        m[0] = mn0; m[1] = mn1;

        float sum0 = 0.f, sum1 = 0.f;
        #pragma unroll
        for (int nt = 0; nt < 8; nt++) {
            s[nt][0] = ex2(s[nt][0] - mn0);
            s[nt][1] = ex2(s[nt][1] - mn0);
            s[nt][2] = ex2(s[nt][2] - mn1);
            s[nt][3] = ex2(s[nt][3] - mn1);
            sum0 += s[nt][0] + s[nt][1];
            sum1 += s[nt][2] + s[nt][3];
        }
        sum0 += __shfl_xor_sync(0xffffffffu, sum0, 1);
        sum0 += __shfl_xor_sync(0xffffffffu, sum0, 2);
        sum1 += __shfl_xor_sync(0xffffffffu, sum1, 1);
        sum1 += __shfl_xor_sync(0xffffffffu, sum1, 2);
        l[0] = l[0] * a0 + sum0;
        l[1] = l[1] * a1 + sum1;

        #pragma unroll
        for (int nt = 0; nt < 8; nt++) {
            o[nt][0] *= a0; o[nt][1] *= a0;
            o[nt][2] *= a1; o[nt][3] *= a1;
        }

        // O += P V   (P fragments packed straight from s regs)
        #pragma unroll
        for (int kt = 0; kt < 4; kt++) {
            uint32_t pf[4];
            pf[0] = packh2(s[2 * kt][0],     s[2 * kt][1]);
            pf[1] = packh2(s[2 * kt][2],     s[2 * kt][3]);
            pf[2] = packh2(s[2 * kt + 1][0], s[2 * kt + 1][1]);
            pf[3] = packh2(s[2 * kt + 1][2], s[2 * kt + 1][3]);
            #pragma unroll
            for (int dp = 0; dp < 4; dp++) {
                uint32_t r4[4];
                const uint32_t addr = vBase +
                    ((kt * 16 + (gg & 1) * 8 + lr) * 72 + dp * 16 + (gg >> 1) * 8) * 2;
                ldsm_x4_t(r4, addr);
                mma16816(o[2 * dp],     pf, r4[0], r4[1]);
                mma16816(o[2 * dp + 1], pf, r4[2], r4[3]);
            }
        }
    }

    // epilogue
    const float inv0 = 1.0f / l[0];
    const float inv1 = 1.0f / l[1];
    const int r0 = qb + mbase + (lane >> 2);
    const int r1 = r0 + 8;
    #pragma unroll
    for (int nt = 0; nt < 8; nt++) {
        const int col = nt * 8 + (lane & 3) * 2;
        if (r0 < T_)
            *reinterpret_cast<__half2*>(Yg + (size_t)r0 * C_ + col) =
                __floats2half2_rn(o[nt][0] * inv0, o[nt][1] * inv0);
        if (r1 < T_)
            *reinterpret_cast<__half2*>(Yg + (size_t)r1 * C_ + col) =
                __floats2half2_rn(o[nt][2] * inv1, o[nt][3] * inv1);
    }
}

// ============================================================
// Host launcher
// ============================================================
extern "C" void kernel_launch(void* const* d_in, const int* in_sizes, int n_in,
                              void* d_out, int out_size)
{
    const float* x    = (const float*)d_in[0];
    const float* Wq   = (const float*)d_in[1];
    const float* Wk   = (const float*)d_in[2];
    const float* Wv   = (const float*)d_in[3];
    const float* Wp   = (const float*)d_in[4];
    const float* qn_w = (const float*)d_in[5];
    const float* qn_b = (const float*)d_in[6];
    const float* kn_w = (const float*)d_in[7];
    const float* kn_b = (const float*)d_in[8];
    const float* fcos = (const float*)d_in[9];
    const float* fsin = (const float*)d_in[10];
    float* out = (float*)d_out;

    float  *q, *k;
    __half *qh, *kh, *vh, *yh, *xh, *wqh, *wkh, *wvh, *wph;
    cudaGetSymbolAddress((void**)&q,   g_q);
    cudaGetSymbolAddress((void**)&k,   g_k);
    cudaGetSymbolAddress((void**)&qh,  g_qh);
    cudaGetSymbolAddress((void**)&kh,  g_kh);
    cudaGetSymbolAddress((void**)&vh,  g_vh);
    cudaGetSymbolAddress((void**)&yh,  g_yh);
    cudaGetSymbolAddress((void**)&xh,  g_xh);
    cudaGetSymbolAddress((void**)&wqh, g_wqh);
    cudaGetSymbolAddress((void**)&wkh, g_wkh);
    cudaGetSymbolAddress((void**)&wvh, g_wvh);
    cudaGetSymbolAddress((void**)&wph, g_wph);

    const int nx4 = (BT_ * C_) / 4;
    const int nw4 = (C_ * C_) / 4;
    f2h_kernel<<<(nx4 + 255) / 256, 256>>>(x,  xh,  nx4);
    f2h_kernel<<<(nw4 + 255) / 256, 256>>>(Wq, wqh, nw4);
    f2h_kernel<<<(nw4 + 255) / 256, 256>>>(Wk, wkh, nw4);
    f2h_kernel<<<(nw4 + 255) / 256, 256>>>(Wv, wvh, nw4);
    f2h_kernel<<<(nw4 + 255) / 256, 256>>>(Wp, wph, nw4);

    const dim3 ggrid(C_ / 128, (BT_ + 127) / 128);   // (6, 130)
    hgemm_mma<float> <<<ggrid, 256>>>(xh, wqh, q,  BT_);
    hgemm_mma<float> <<<ggrid, 256>>>(xh, wkh, k,  BT_);
    hgemm_mma<__half><<<ggrid, 256>>>(xh, wvh, vh, BT_);

    ln_rope_h<<<BT_, 256>>>(q, qh, qn_w, qn_b, fcos, fsin, QSCALE);
    ln_rope_h<<<BT_, 256>>>(k, kh, kn_w, kn_b, fcos, fsin, 1.0f);

    const dim3 fgrid((T_ + 63) / 64, B_ * H_);       // (17, 192)
    flash_mma<<<fgrid, 128>>>(qh, kh, vh, yh);

    hgemm_mma<float><<<ggrid, 256>>>(yh, wph, out, BT_);
}

// round 5
// speedup vs baseline: 6.9154x; 1.0314x over previous
#include <cuda_runtime.h>
#include <cuda_fp16.h>
#include <stdint.h>
#include <math.h>

// Problem constants
#define B_      16
#define T_      1033
#define C_      768
#define H_      12
#define HD_     64
#define OFFSET_ 9
#define BT_     (B_ * T_)          // 16528 rows
#define QSCALE  0.180336884f       // (1/sqrt(64)) * log2(e)

// ---------------- scratch ----------------
__device__ float  g_q [(size_t)BT_ * C_];
__device__ float  g_k [(size_t)BT_ * C_];
__device__ __half g_qh[(size_t)BT_ * C_];
__device__ __half g_kh[(size_t)BT_ * C_];
__device__ __half g_vh[(size_t)BT_ * C_];
__device__ __half g_yh[(size_t)BT_ * C_];
__device__ __half g_xh[(size_t)BT_ * C_];
__device__ __half g_wqh[(size_t)C_ * C_];
__device__ __half g_wkh[(size_t)C_ * C_];
__device__ __half g_wvh[(size_t)C_ * C_];
__device__ __half g_wph[(size_t)C_ * C_];

// ---------------- PTX helpers ----------------
__device__ __forceinline__ uint32_t smem_u32(const void* p) {
    uint32_t a;
    asm("{ .reg .u64 t; cvta.to.shared.u64 t, %1; cvt.u32.u64 %0, t; }" : "=r"(a) : "l"(p));
    return a;
}
__device__ __forceinline__ void ldsm_x4(uint32_t* r, uint32_t addr) {
    asm volatile("ldmatrix.sync.aligned.m8n8.x4.shared.b16 {%0,%1,%2,%3}, [%4];"
                 : "=r"(r[0]), "=r"(r[1]), "=r"(r[2]), "=r"(r[3]) : "r"(addr));
}
__device__ __forceinline__ void ldsm_x4_t(uint32_t* r, uint32_t addr) {
    asm volatile("ldmatrix.sync.aligned.m8n8.x4.trans.shared.b16 {%0,%1,%2,%3}, [%4];"
                 : "=r"(r[0]), "=r"(r[1]), "=r"(r[2]), "=r"(r[3]) : "r"(addr));
}
__device__ __forceinline__ void mma16816(float* c, const uint32_t* a, uint32_t b0, uint32_t b1) {
    asm volatile("mma.sync.aligned.m16n8k16.row.col.f32.f16.f16.f32 "
                 "{%0,%1,%2,%3}, {%4,%5,%6,%7}, {%8,%9}, {%0,%1,%2,%3};"
                 : "+f"(c[0]), "+f"(c[1]), "+f"(c[2]), "+f"(c[3])
                 : "r"(a[0]), "r"(a[1]), "r"(a[2]), "r"(a[3]), "r"(b0), "r"(b1));
}
__device__ __forceinline__ float ex2(float x) {
    float y;
    asm("ex2.approx.ftz.f32 %0, %1;" : "=f"(y) : "f"(x));
    return y;
}
__device__ __forceinline__ uint32_t packh2(float a, float b) {
    __half2 h = __floats2half2_rn(a, b);
    return *reinterpret_cast<uint32_t*>(&h);
}
__device__ __forceinline__ void store2(float* p, float a, float b) {
    *reinterpret_cast<float2*>(p) = make_float2(a, b);
}
__device__ __forceinline__ void store2(__half* p, float a, float b) {
    *reinterpret_cast<__half2*>(p) = __floats2half2_rn(a, b);
}
// cp.async 16B with zero-fill when invalid
__device__ __forceinline__ void cpa16(uint32_t dst, const void* src, bool valid) {
    const int sz = valid ? 16 : 0;
    asm volatile("cp.async.ca.shared.global [%0], [%1], 16, %2;"
                 :: "r"(dst), "l"(src), "r"(sz) : "memory");
}
#define CP_COMMIT() asm volatile("cp.async.commit_group;" ::: "memory")
#define CP_WAIT(n)  asm volatile("cp.async.wait_group %0;" :: "n"(n) : "memory")

// ============================================================
// fp32 -> fp16 conversion
// ============================================================
__global__ __launch_bounds__(256)
void f2h_kernel(const float* __restrict__ in, __half* __restrict__ out, int n4)
{
    int i = blockIdx.x * blockDim.x + threadIdx.x;
    if (i < n4) {
        float4 v = reinterpret_cast<const float4*>(in)[i];
        uint2 pk;
        pk.x = packh2(v.x, v.y);
        pk.y = packh2(v.z, v.w);
        reinterpret_cast<uint2*>(out)[i] = pk;
    }
}

// ============================================================
// HGEMM (NT), cp.async 2-stage pipeline.
// C[m,n] = sum_k A[m,k]*W[n,k]; CTA 128x128, BK=32, 8 warps.
// ============================================================
#define NKT_G (C_ / 32)   // 24

template<typename OutT>
__global__ __launch_bounds__(256)
void hgemm_mma(const __half* __restrict__ A, const __half* __restrict__ Bw,
               OutT* __restrict__ Cm, int M)
{
    __shared__ __half As[2][128][40];
    __shared__ __half Bs[2][128][40];

    const int tid  = threadIdx.x;
    const int lane = tid & 31, wid = tid >> 5;
    const int wm   = (wid >> 2) * 64;
    const int wn   = (wid & 3) * 32;
    const int bm   = blockIdx.y * 128, bn = blockIdx.x * 128;
    const int gg = lane >> 3, lr = lane & 7;

    // copy mapping: 512 chunks of 16B per (A|B) tile; thread does 2 of each
    const int r0  = tid >> 1;                // 0..127
    const int cb0 = (tid & 1) * 16;          // 0 or 16 (half index)

    float acc[4][4][4];
    #pragma unroll
    for (int i = 0; i < 4; i++)
        #pragma unroll
        for (int j = 0; j < 4; j++)
            #pragma unroll
            for (int r = 0; r < 4; r++) acc[i][j][r] = 0.f;

    const uint32_t aB0 = smem_u32(&As[0][0][0]);
    const uint32_t bB0 = smem_u32(&Bs[0][0][0]);
    const uint32_t stageBytes = 128 * 40 * 2;

    auto copy_tiles = [&](int kt, int st) {
        const uint32_t aDst = aB0 + st * stageBytes + (r0 * 40 + cb0) * 2;
        const uint32_t bDst = bB0 + st * stageBytes + (r0 * 40 + cb0) * 2;
        const __half* aSrc = A  + (size_t)(bm + r0) * C_ + kt * 32 + cb0;
        const __half* bSrc = Bw + (size_t)(bn + r0) * C_ + kt * 32 + cb0;
        cpa16(aDst,      aSrc,     bm + r0 < M);
        cpa16(aDst + 16, aSrc + 8, bm + r0 < M);
        cpa16(bDst,      bSrc,     true);
        cpa16(bDst + 16, bSrc + 8, true);
    };

    copy_tiles(0, 0);
    CP_COMMIT();

    for (int kt = 0; kt < NKT_G; kt++) {
        const int cur = kt & 1;
        if (kt + 1 < NKT_G) {
            copy_tiles(kt + 1, (kt + 1) & 1);
            CP_COMMIT();
            CP_WAIT(1);
        } else {
            CP_WAIT(0);
        }
        __syncthreads();

        const uint32_t aBase = aB0 + cur * stageBytes;
        const uint32_t bBase = bB0 + cur * stageBytes;
        #pragma unroll
        for (int ks = 0; ks < 32; ks += 16) {
            uint32_t af[4][4], bf[4][2];
            #pragma unroll
            for (int i = 0; i < 4; i++) {
                const uint32_t addr = aBase +
                    ((wm + i * 16 + (gg & 1) * 8 + lr) * 40 + ks + (gg >> 1) * 8) * 2;
                ldsm_x4(af[i], addr);
            }
            #pragma unroll
            for (int np = 0; np < 2; np++) {
                uint32_t r4[4];
                const uint32_t addr = bBase +
                    ((wn + np * 16 + (gg >> 1) * 8 + lr) * 40 + ks + (gg & 1) * 8) * 2;
                ldsm_x4(r4, addr);
                bf[2 * np][0]     = r4[0]; bf[2 * np][1]     = r4[1];
                bf[2 * np + 1][0] = r4[2]; bf[2 * np + 1][1] = r4[3];
            }
            #pragma unroll
            for (int i = 0; i < 4; i++)
                #pragma unroll
                for (int j = 0; j < 4; j++)
                    mma16816(acc[i][j], af[i], bf[j][0], bf[j][1]);
        }
        __syncthreads();
    }

    #pragma unroll
    for (int i = 0; i < 4; i++) {
        const int row0 = bm + wm + i * 16 + (lane >> 2);
        #pragma unroll
        for (int j = 0; j < 4; j++) {
            const int col = bn + wn + j * 8 + (lane & 3) * 2;
            if (row0 < M)     store2(Cm + (size_t)row0 * C_ + col,       acc[i][j][0], acc[i][j][1]);
            if (row0 + 8 < M) store2(Cm + (size_t)(row0 + 8) * C_ + col, acc[i][j][2], acc[i][j][3]);
        }
    }
}

// ============================================================
// LayerNorm + axial RoPE: warp-per-row, fp32 in -> fp16 out
// 128 threads = 4 rows per block; no smem, warp-reduce only.
// ============================================================
__global__ __launch_bounds__(128)
void ln_rope_h(const float* __restrict__ buf, __half* __restrict__ outh,
               const float* __restrict__ w, const float* __restrict__ bvec,
               const float* __restrict__ fcos, const float* __restrict__ fsin,
               float oscale)
{
    const int warp = threadIdx.x >> 5, lane = threadIdx.x & 31;
    const int row  = blockIdx.x * 4 + warp;
    if (row >= BT_) return;

    const float4* in4 = reinterpret_cast<const float4*>(buf + (size_t)row * C_);
    float4 v[6];
    float sum = 0.f, sq = 0.f;
    #pragma unroll
    for (int i = 0; i < 6; i++) {
        v[i] = in4[lane + 32 * i];
        sum += v[i].x + v[i].y + v[i].z + v[i].w;
        sq  += v[i].x * v[i].x + v[i].y * v[i].y + v[i].z * v[i].z + v[i].w * v[i].w;
    }
    #pragma unroll
    for (int o = 16; o > 0; o >>= 1) {
        sum += __shfl_xor_sync(0xffffffffu, sum, o);
        sq  += __shfl_xor_sync(0xffffffffu, sq,  o);
    }
    const float mn = sum / (float)C_;
    const float rs = rsqrtf(sq / (float)C_ - mn * mn + 1e-5f);

    const int t = row % T_;
    const bool rope = (t >= OFFSET_);
    const int p = t - OFFSET_;

    const float4* w4 = reinterpret_cast<const float4*>(w);
    const float4* b4 = reinterpret_cast<const float4*>(bvec);
    uint2* out2 = reinterpret_cast<uint2*>(outh + (size_t)row * C_);

    #pragma unroll
    for (int i = 0; i < 6; i++) {
        const int f = lane + 32 * i;           // float4 index, 0..191
        const float4 wv = w4[f], bv = b4[f];
        float e0 = (v[i].x - mn) * rs * wv.x + bv.x;
        float o0 = (v[i].y - mn) * rs * wv.y + bv.y;
        float e1 = (v[i].z - mn) * rs * wv.z + bv.z;
        float o1 = (v[i].w - mn) * rs * wv.w + bv.w;
        if (rope) {
            const int pr0 = (2 * f) & 31, pr1 = (2 * f + 1) & 31;
            const float c0 = fcos[p * 32 + pr0], s0 = fsin[p * 32 + pr0];
            const float c1 = fcos[p * 32 + pr1], s1 = fsin[p * 32 + pr1];
            float ne0 = e0 * c0 - o0 * s0, no0 = e0 * s0 + o0 * c0;
            float ne1 = e1 * c1 - o1 * s1, no1 = e1 * s1 + o1 * c1;
            e0 = ne0; o0 = no0; e1 = ne1; o1 = no1;
        }
        uint2 pk;
        pk.x = packh2(e0 * oscale, o0 * oscale);
        pk.y = packh2(e1 * oscale, o1 * oscale);
        out2[f] = pk;
    }
}

// ============================================================
// Flash attention via mma.sync, cp.async double-buffered K/V.
// CTA: 64 queries, 4 warps; key tiles of 64.
// ============================================================
__global__ __launch_bounds__(128)
void flash_mma(const __half* __restrict__ Qh, const __half* __restrict__ Kh,
               const __half* __restrict__ Vh, __half* __restrict__ Yh)
{
    __shared__ __half Qs[64][72];
    __shared__ __half Ks[2][64][72];
    __shared__ __half Vs[2][64][72];

    const int tid  = threadIdx.x, lane = tid & 31, wid = tid >> 5;
    const int qb   = blockIdx.x * 64;
    const int bh   = blockIdx.y;
    const int b    = bh / H_, h = bh % H_;
    const size_t base = (size_t)b * T_ * C_ + h * HD_;
    const __half* Qg = Qh + base;
    const __half* Kg = Kh + base;
    const __half* Vg = Vh + base;
    __half*       Yg = Yh + base;

    const uint32_t qB = smem_u32(&Qs[0][0]);
    const uint32_t kB = smem_u32(&Ks[0][0][0]);
    const uint32_t vB = smem_u32(&Vs[0][0][0]);
    const uint32_t stageB = 64 * 72 * 2;

    // copy mapping: 512 chunks of 16B per tile, 4 per thread
    const int cr  = tid >> 1;               // 0..63
    const int ccb = (tid & 1) * 32;         // half index 0 or 32

    auto copy_kv = [&](int kb, int st) {
        const uint32_t kDst = kB + st * stageB + (cr * 72 + ccb) * 2;
        const uint32_t vDst = vB + st * stageB + (cr * 72 + ccb) * 2;
        const __half* kSrc = Kg + (size_t)(kb + cr) * C_ + ccb;
        const __half* vSrc = Vg + (size_t)(kb + cr) * C_ + ccb;
        const bool ok = (kb + cr) < T_;
        cpa16(kDst,      kSrc,      ok);
        cpa16(kDst + 16, kSrc + 8,  ok);
        cpa16(kDst + 32, kSrc + 16, ok);
        cpa16(kDst + 48, kSrc + 24, ok);
        cpa16(vDst,      vSrc,      ok);
        cpa16(vDst + 16, vSrc + 8,  ok);
        cpa16(vDst + 32, vSrc + 16, ok);
        cpa16(vDst + 48, vSrc + 24, ok);
    };

    // prologue: Q + KV tile 0 in group 0
    {
        const uint32_t qDst = qB + (cr * 72 + ccb) * 2;
        const __half* qSrc = Qg + (size_t)(qb + cr) * C_ + ccb;
        const bool ok = (qb + cr) < T_;
        cpa16(qDst,      qSrc,      ok);
        cpa16(qDst + 16, qSrc + 8,  ok);
        cpa16(qDst + 32, qSrc + 16, ok);
        cpa16(qDst + 48, qSrc + 24, ok);
        copy_kv(0, 0);
        CP_COMMIT();
    }

    const int gg = lane >> 3, lr = lane & 7;
    const int mbase = wid * 16;
    uint32_t qf[4][4];

    float m[2] = { -1e30f, -1e30f };
    float l[2] = { 0.f, 0.f };
    float o[8][4];
    #pragma unroll
    for (int nt = 0; nt < 8; nt++)
        #pragma unroll
        for (int r = 0; r < 4; r++) o[nt][r] = 0.f;

    const int nKT = (T_ + 63) / 64;   // 17
    for (int kbi = 0; kbi < nKT; kbi++) {
        const int kb = kbi * 64;
        const int cur = kbi & 1;
        if (kbi + 1 < nKT) {
            copy_kv(kb + 64, (kbi + 1) & 1);
            CP_COMMIT();
            CP_WAIT(1);
        } else {
            CP_WAIT(0);
        }
        __syncthreads();

        if (kbi == 0) {
            #pragma unroll
            for (int kt = 0; kt < 4; kt++) {
                const uint32_t addr = qB +
                    ((mbase + (gg & 1) * 8 + lr) * 72 + kt * 16 + (gg >> 1) * 8) * 2;
                ldsm_x4(qf[kt], addr);
            }
        }

        const uint32_t kBase = kB + cur * stageB;
        const uint32_t vBase = vB + cur * stageB;

        // S = Q K^T
        float s[8][4];
        #pragma unroll
        for (int nt = 0; nt < 8; nt++)
            #pragma unroll
            for (int r = 0; r < 4; r++) s[nt][r] = 0.f;

        #pragma unroll
        for (int np = 0; np < 4; np++) {
            #pragma unroll
            for (int kt = 0; kt < 4; kt++) {
                uint32_t r4[4];
                const uint32_t addr = kBase +
                    ((np * 16 + (gg >> 1) * 8 + lr) * 72 + kt * 16 + (gg & 1) * 8) * 2;
                ldsm_x4(r4, addr);
                mma16816(s[2 * np],     qf[kt], r4[0], r4[1]);
                mma16816(s[2 * np + 1], qf[kt], r4[2], r4[3]);
            }
        }

        if (kb + 64 > T_) {
            #pragma unroll
            for (int nt = 0; nt < 8; nt++) {
                const int c0 = kb + nt * 8 + (lane & 3) * 2;
                if (c0 >= T_)     { s[nt][0] = -1e30f; s[nt][2] = -1e30f; }
                if (c0 + 1 >= T_) { s[nt][1] = -1e30f; s[nt][3] = -1e30f; }
            }
        }

        float mx0 = -1e30f, mx1 = -1e30f;
        #pragma unroll
        for (int nt = 0; nt < 8; nt++) {
            mx0 = fmaxf(mx0, fmaxf(s[nt][0], s[nt][1]));
            mx1 = fmaxf(mx1, fmaxf(s[nt][2], s[nt][3]));
        }
        mx0 = fmaxf(mx0, __shfl_xor_sync(0xffffffffu, mx0, 1));
        mx0 = fmaxf(mx0, __shfl_xor_sync(0xffffffffu, mx0, 2));
        mx1 = fmaxf(mx1, __shfl_xor_sync(0xffffffffu, mx1, 1));
        mx1 = fmaxf(mx1, __shfl_xor_sync(0xffffffffu, mx1, 2));

        const float mn0 = fmaxf(m[0], mx0);
        const float mn1 = fmaxf(m[1], mx1);
        const float a0 = ex2(m[0] - mn0);
        const float a1 = ex2(m[1] - mn1);
        m[0] = mn0; m[1] = mn1;

        float sum0 = 0.f, sum1 = 0.f;
        #pragma unroll
        for (int nt = 0; nt < 8; nt++) {
            s[nt][0] = ex2(s[nt][0] - mn0);
            s[nt][1] = ex2(s[nt][1] - mn0);
            s[nt][2] = ex2(s[nt][2] - mn1);
            s[nt][3] = ex2(s[nt][3] - mn1);
            sum0 += s[nt][0] + s[nt][1];
            sum1 += s[nt][2] + s[nt][3];
        }
        sum0 += __shfl_xor_sync(0xffffffffu, sum0, 1);
        sum0 += __shfl_xor_sync(0xffffffffu, sum0, 2);
        sum1 += __shfl_xor_sync(0xffffffffu, sum1, 1);
        sum1 += __shfl_xor_sync(0xffffffffu, sum1, 2);
        l[0] = l[0] * a0 + sum0;
        l[1] = l[1] * a1 + sum1;

        #pragma unroll
        for (int nt = 0; nt < 8; nt++) {
            o[nt][0] *= a0; o[nt][1] *= a0;
            o[nt][2] *= a1; o[nt][3] *= a1;
        }

        #pragma unroll
        for (int kt = 0; kt < 4; kt++) {
            uint32_t pf[4];
            pf[0] = packh2(s[2 * kt][0],     s[2 * kt][1]);
            pf[1] = packh2(s[2 * kt][2],     s[2 * kt][3]);
            pf[2] = packh2(s[2 * kt + 1][0], s[2 * kt + 1][1]);
            pf[3] = packh2(s[2 * kt + 1][2], s[2 * kt + 1][3]);
            #pragma unroll
            for (int dp = 0; dp < 4; dp++) {
                uint32_t r4[4];
                const uint32_t addr = vBase +
                    ((kt * 16 + (gg & 1) * 8 + lr) * 72 + dp * 16 + (gg >> 1) * 8) * 2;
                ldsm_x4_t(r4, addr);
                mma16816(o[2 * dp],     pf, r4[0], r4[1]);
                mma16816(o[2 * dp + 1], pf, r4[2], r4[3]);
            }
        }
        __syncthreads();
    }

    const float inv0 = 1.0f / l[0];
    const float inv1 = 1.0f / l[1];
    const int r0 = qb + mbase + (lane >> 2);
    const int r1 = r0 + 8;
    #pragma unroll
    for (int nt = 0; nt < 8; nt++) {
        const int col = nt * 8 + (lane & 3) * 2;
        if (r0 < T_)
            *reinterpret_cast<__half2*>(Yg + (size_t)r0 * C_ + col) =
                __floats2half2_rn(o[nt][0] * inv0, o[nt][1] * inv0);
        if (r1 < T_)
            *reinterpret_cast<__half2*>(Yg + (size_t)r1 * C_ + col) =
                __floats2half2_rn(o[nt][2] * inv1, o[nt][3] * inv1);
    }
}

// ============================================================
// Host launcher
// ============================================================
extern "C" void kernel_launch(void* const* d_in, const int* in_sizes, int n_in,
                              void* d_out, int out_size)
{
    const float* x    = (const float*)d_in[0];
    const float* Wq   = (const float*)d_in[1];
    const float* Wk   = (const float*)d_in[2];
    const float* Wv   = (const float*)d_in[3];
    const float* Wp   = (const float*)d_in[4];
    const float* qn_w = (const float*)d_in[5];
    const float* qn_b = (const float*)d_in[6];
    const float* kn_w = (const float*)d_in[7];
    const float* kn_b = (const float*)d_in[8];
    const float* fcos = (const float*)d_in[9];
    const float* fsin = (const float*)d_in[10];
    float* out = (float*)d_out;

    float  *q, *k;
    __half *qh, *kh, *vh, *yh, *xh, *wqh, *wkh, *wvh, *wph;
    cudaGetSymbolAddress((void**)&q,   g_q);
    cudaGetSymbolAddress((void**)&k,   g_k);
    cudaGetSymbolAddress((void**)&qh,  g_qh);
    cudaGetSymbolAddress((void**)&kh,  g_kh);
    cudaGetSymbolAddress((void**)&vh,  g_vh);
    cudaGetSymbolAddress((void**)&yh,  g_yh);
    cudaGetSymbolAddress((void**)&xh,  g_xh);
    cudaGetSymbolAddress((void**)&wqh, g_wqh);
    cudaGetSymbolAddress((void**)&wkh, g_wkh);
    cudaGetSymbolAddress((void**)&wvh, g_wvh);
    cudaGetSymbolAddress((void**)&wph, g_wph);

    const int nx4 = (BT_ * C_) / 4;
    const int nw4 = (C_ * C_) / 4;
    f2h_kernel<<<(nx4 + 255) / 256, 256>>>(x,  xh,  nx4);
    f2h_kernel<<<(nw4 + 255) / 256, 256>>>(Wq, wqh, nw4);
    f2h_kernel<<<(nw4 + 255) / 256, 256>>>(Wk, wkh, nw4);
    f2h_kernel<<<(nw4 + 255) / 256, 256>>>(Wv, wvh, nw4);
    f2h_kernel<<<(nw4 + 255) / 256, 256>>>(Wp, wph, nw4);

    const dim3 ggrid(C_ / 128, (BT_ + 127) / 128);   // (6, 130)
    hgemm_mma<float> <<<ggrid, 256>>>(xh, wqh, q,  BT_);
    hgemm_mma<float> <<<ggrid, 256>>>(xh, wkh, k,  BT_);
    hgemm_mma<__half><<<ggrid, 256>>>(xh, wvh, vh, BT_);

    const int lgrid = (BT_ + 3) / 4;
    ln_rope_h<<<lgrid, 128>>>(q, qh, qn_w, qn_b, fcos, fsin, QSCALE);
    ln_rope_h<<<lgrid, 128>>>(k, kh, kn_w, kn_b, fcos, fsin, 1.0f);

    const dim3 fgrid((T_ + 63) / 64, B_ * H_);       // (17, 192)
    flash_mma<<<fgrid, 128>>>(qh, kh, vh, yh);

    hgemm_mma<float><<<ggrid, 256>>>(yh, wph, out, BT_);
}

// round 6
// speedup vs baseline: 7.4430x; 1.0763x over previous
#include <cuda_runtime.h>
#include <cuda_fp16.h>
#include <stdint.h>
#include <math.h>

// Problem constants
#define B_      16
#define T_      1033
#define C_      768
#define H_      12
#define HD_     64
#define OFFSET_ 9
#define BT_     (B_ * T_)          // 16528 rows
#define QSCALE  0.180336884f       // (1/sqrt(64)) * log2(e)

// ---------------- scratch ----------------
__device__ float  g_q [(size_t)BT_ * C_];
__device__ float  g_k [(size_t)BT_ * C_];
__device__ __half g_qh[(size_t)BT_ * C_];
__device__ __half g_kh[(size_t)BT_ * C_];
__device__ __half g_vh[(size_t)BT_ * C_];
__device__ __half g_yh[(size_t)BT_ * C_];
__device__ __half g_xh[(size_t)BT_ * C_];
__device__ __half g_wqh[(size_t)C_ * C_];
__device__ __half g_wkh[(size_t)C_ * C_];
__device__ __half g_wvh[(size_t)C_ * C_];
__device__ __half g_wph[(size_t)C_ * C_];

// ---------------- PTX helpers ----------------
__device__ __forceinline__ uint32_t smem_u32(const void* p) {
    uint32_t a;
    asm("{ .reg .u64 t; cvta.to.shared.u64 t, %1; cvt.u32.u64 %0, t; }" : "=r"(a) : "l"(p));
    return a;
}
__device__ __forceinline__ void ldsm_x4(uint32_t* r, uint32_t addr) {
    asm volatile("ldmatrix.sync.aligned.m8n8.x4.shared.b16 {%0,%1,%2,%3}, [%4];"
                 : "=r"(r[0]), "=r"(r[1]), "=r"(r[2]), "=r"(r[3]) : "r"(addr));
}
__device__ __forceinline__ void ldsm_x4_t(uint32_t* r, uint32_t addr) {
    asm volatile("ldmatrix.sync.aligned.m8n8.x4.trans.shared.b16 {%0,%1,%2,%3}, [%4];"
                 : "=r"(r[0]), "=r"(r[1]), "=r"(r[2]), "=r"(r[3]) : "r"(addr));
}
__device__ __forceinline__ void mma16816(float* c, const uint32_t* a, uint32_t b0, uint32_t b1) {
    asm volatile("mma.sync.aligned.m16n8k16.row.col.f32.f16.f16.f32 "
                 "{%0,%1,%2,%3}, {%4,%5,%6,%7}, {%8,%9}, {%0,%1,%2,%3};"
                 : "+f"(c[0]), "+f"(c[1]), "+f"(c[2]), "+f"(c[3])
                 : "r"(a[0]), "r"(a[1]), "r"(a[2]), "r"(a[3]), "r"(b0), "r"(b1));
}
__device__ __forceinline__ float ex2(float x) {
    float y;
    asm("ex2.approx.ftz.f32 %0, %1;" : "=f"(y) : "f"(x));
    return y;
}
__device__ __forceinline__ uint32_t packh2(float a, float b) {
    __half2 h = __floats2half2_rn(a, b);
    return *reinterpret_cast<uint32_t*>(&h);
}
__device__ __forceinline__ void store2(float* p, float a, float b) {
    *reinterpret_cast<float2*>(p) = make_float2(a, b);
}
__device__ __forceinline__ void cpa16(uint32_t dst, const void* src, bool valid) {
    const int sz = valid ? 16 : 0;
    asm volatile("cp.async.ca.shared.global [%0], [%1], 16, %2;"
                 :: "r"(dst), "l"(src), "r"(sz) : "memory");
}
#define CP_COMMIT() asm volatile("cp.async.commit_group;" ::: "memory")
#define CP_WAIT(n)  asm volatile("cp.async.wait_group %0;" :: "n"(n) : "memory")

// ============================================================
// fp32 -> fp16 conversions
// ============================================================
__global__ __launch_bounds__(256)
void f2h_kernel(const float* __restrict__ in, __half* __restrict__ out, int n4)
{
    int i = blockIdx.x * blockDim.x + threadIdx.x;
    if (i < n4) {
        float4 v = reinterpret_cast<const float4*>(in)[i];
        uint2 pk;
        pk.x = packh2(v.x, v.y);
        pk.y = packh2(v.z, v.w);
        reinterpret_cast<uint2*>(out)[i] = pk;
    }
}
// all 4 weight matrices in one launch (blockIdx.y selects)
__global__ __launch_bounds__(256)
void f2h_w4(const float* w0, const float* w1, const float* w2, const float* w3,
            __half* o0, __half* o1, __half* o2, __half* o3, int n4)
{
    const float* in;
    __half* out;
    switch (blockIdx.y) {
        case 0: in = w0; out = o0; break;
        case 1: in = w1; out = o1; break;
        case 2: in = w2; out = o2; break;
        default: in = w3; out = o3; break;
    }
    int i = blockIdx.x * blockDim.x + threadIdx.x;
    if (i < n4) {
        float4 v = reinterpret_cast<const float4*>(in)[i];
        uint2 pk;
        pk.x = packh2(v.x, v.y);
        pk.y = packh2(v.z, v.w);
        reinterpret_cast<uint2*>(out)[i] = pk;
    }
}

// ============================================================
// GEMM mainloop pieces (shared by qkv & proj kernels)
// 4-stage cp.async circular buffer, single __syncthreads per tile.
// smem layout per stage: A(128x40 half) then B(128x40 half) = 20480 B
// ============================================================
#define NKT_G   (C_ / 32)          // 24
#define GSTAGE  4
#define GSTB    20480u
#define GA_OFF  0u
#define GB_OFF  10240u
#define G_SMEM  (GSTAGE * GSTB)    // 81920

struct GemmCtx {
    uint32_t sB;          // smem base
    const __half* A;
    const __half* Bw;
    int bm, bn, M;
    int r0, cb0;          // copy mapping
};

__device__ __forceinline__ void g_copy(const GemmCtx& c, int kt, int st) {
    const uint32_t aDst = c.sB + st * GSTB + GA_OFF + (c.r0 * 40 + c.cb0) * 2;
    const uint32_t bDst = c.sB + st * GSTB + GB_OFF + (c.r0 * 40 + c.cb0) * 2;
    const __half* aSrc = c.A  + (size_t)(c.bm + c.r0) * C_ + kt * 32 + c.cb0;
    const __half* bSrc = c.Bw + (size_t)(c.bn + c.r0) * C_ + kt * 32 + c.cb0;
    const bool okA = (c.bm + c.r0) < c.M;
    cpa16(aDst,      aSrc,     okA);
    cpa16(aDst + 16, aSrc + 8, okA);
    cpa16(bDst,      bSrc,     true);
    cpa16(bDst + 16, bSrc + 8, true);
}

// full mainloop: fills acc[4][4][4]
__device__ __forceinline__ void g_mainloop(const GemmCtx& c, int wm, int wn,
                                           int gg, int lr, float acc[4][4][4]) {
    #pragma unroll
    for (int s = 0; s < GSTAGE - 1; s++) {
        g_copy(c, s, s);
        CP_COMMIT();
    }
    for (int kt = 0; kt < NKT_G; kt++) {
        CP_WAIT(GSTAGE - 2);
        __syncthreads();
        const uint32_t aBase = c.sB + (kt & 3) * GSTB + GA_OFF;
        const uint32_t bBase = c.sB + (kt & 3) * GSTB + GB_OFF;
        #pragma unroll
        for (int ks = 0; ks < 32; ks += 16) {
            uint32_t af[4][4], bf[4][2];
            #pragma unroll
            for (int i = 0; i < 4; i++) {
                const uint32_t addr = aBase +
                    ((wm + i * 16 + (gg & 1) * 8 + lr) * 40 + ks + (gg >> 1) * 8) * 2;
                ldsm_x4(af[i], addr);
            }
            #pragma unroll
            for (int np = 0; np < 2; np++) {
                uint32_t r4[4];
                const uint32_t addr = bBase +
                    ((wn + np * 16 + (gg >> 1) * 8 + lr) * 40 + ks + (gg & 1) * 8) * 2;
                ldsm_x4(r4, addr);
                bf[2 * np][0]     = r4[0]; bf[2 * np][1]     = r4[1];
                bf[2 * np + 1][0] = r4[2]; bf[2 * np + 1][1] = r4[3];
            }
            #pragma unroll
            for (int i = 0; i < 4; i++)
                #pragma unroll
                for (int j = 0; j < 4; j++)
                    mma16816(acc[i][j], af[i], bf[j][0], bf[j][1]);
        }
        if (kt + GSTAGE - 1 < NKT_G)
            g_copy(c, kt + GSTAGE - 1, (kt + GSTAGE - 1) & 3);
        CP_COMMIT();
    }
}

// ============================================================
// Fused QKV GEMM: blockIdx.x = wsel*6 + nblk
// Q,K -> fp32; V -> fp16.
// ============================================================
__global__ __launch_bounds__(256)
void qkv_gemm(const __half* __restrict__ A,
              const __half* __restrict__ Wq, const __half* __restrict__ Wk,
              const __half* __restrict__ Wv,
              float* __restrict__ Qo, float* __restrict__ Ko,
              __half* __restrict__ Vo, int M)
{
    extern __shared__ char smem[];
    const int tid  = threadIdx.x;
    const int lane = tid & 31, wid = tid >> 5;
    const int wm   = (wid >> 2) * 64;
    const int wn   = (wid & 3) * 32;
    const int wsel = blockIdx.x / 6;
    const int bn   = (blockIdx.x % 6) * 128;
    const int bm   = blockIdx.y * 128;
    const int gg = lane >> 3, lr = lane & 7;

    GemmCtx c;
    c.sB = smem_u32(smem);
    c.A  = A;
    c.Bw = (wsel == 0) ? Wq : (wsel == 1) ? Wk : Wv;
    c.bm = bm; c.bn = bn; c.M = M;
    c.r0 = tid >> 1; c.cb0 = (tid & 1) * 16;

    float acc[4][4][4];
    #pragma unroll
    for (int i = 0; i < 4; i++)
        #pragma unroll
        for (int j = 0; j < 4; j++)
            #pragma unroll
            for (int r = 0; r < 4; r++) acc[i][j][r] = 0.f;

    g_mainloop(c, wm, wn, gg, lr, acc);

    if (wsel < 2) {
        float* Cm = wsel ? Ko : Qo;
        #pragma unroll
        for (int i = 0; i < 4; i++) {
            const int row0 = bm + wm + i * 16 + (lane >> 2);
            #pragma unroll
            for (int j = 0; j < 4; j++) {
                const int col = bn + wn + j * 8 + (lane & 3) * 2;
                if (row0 < M)     store2(Cm + (size_t)row0 * C_ + col,       acc[i][j][0], acc[i][j][1]);
                if (row0 + 8 < M) store2(Cm + (size_t)(row0 + 8) * C_ + col, acc[i][j][2], acc[i][j][3]);
            }
        }
    } else {
        #pragma unroll
        for (int i = 0; i < 4; i++) {
            const int row0 = bm + wm + i * 16 + (lane >> 2);
            #pragma unroll
            for (int j = 0; j < 4; j++) {
                const int col = bn + wn + j * 8 + (lane & 3) * 2;
                if (row0 < M)
                    *reinterpret_cast<__half2*>(Vo + (size_t)row0 * C_ + col) =
                        __floats2half2_rn(acc[i][j][0], acc[i][j][1]);
                if (row0 + 8 < M)
                    *reinterpret_cast<__half2*>(Vo + (size_t)(row0 + 8) * C_ + col) =
                        __floats2half2_rn(acc[i][j][2], acc[i][j][3]);
            }
        }
    }
}

// ============================================================
// Projection GEMM (fp32 out)
// ============================================================
__global__ __launch_bounds__(256)
void proj_gemm(const __half* __restrict__ A, const __half* __restrict__ Bw,
               float* __restrict__ Cm, int M)
{
    extern __shared__ char smem[];
    const int tid  = threadIdx.x;
    const int lane = tid & 31, wid = tid >> 5;
    const int wm   = (wid >> 2) * 64;
    const int wn   = (wid & 3) * 32;
    const int bn   = blockIdx.x * 128;
    const int bm   = blockIdx.y * 128;
    const int gg = lane >> 3, lr = lane & 7;

    GemmCtx c;
    c.sB = smem_u32(smem);
    c.A = A; c.Bw = Bw;
    c.bm = bm; c.bn = bn; c.M = M;
    c.r0 = tid >> 1; c.cb0 = (tid & 1) * 16;

    float acc[4][4][4];
    #pragma unroll
    for (int i = 0; i < 4; i++)
        #pragma unroll
        for (int j = 0; j < 4; j++)
            #pragma unroll
            for (int r = 0; r < 4; r++) acc[i][j][r] = 0.f;

    g_mainloop(c, wm, wn, gg, lr, acc);

    #pragma unroll
    for (int i = 0; i < 4; i++) {
        const int row0 = bm + wm + i * 16 + (lane >> 2);
        #pragma unroll
        for (int j = 0; j < 4; j++) {
            const int col = bn + wn + j * 8 + (lane & 3) * 2;
            if (row0 < M)     store2(Cm + (size_t)row0 * C_ + col,       acc[i][j][0], acc[i][j][1]);
            if (row0 + 8 < M) store2(Cm + (size_t)(row0 + 8) * C_ + col, acc[i][j][2], acc[i][j][3]);
        }
    }
}

// ============================================================
// LayerNorm + axial RoPE, both Q and K in one launch (blockIdx.y)
// warp-per-row, fp32 in -> fp16 out
// ============================================================
__global__ __launch_bounds__(128)
void ln_rope2(const float* __restrict__ qbuf, const float* __restrict__ kbuf,
              __half* __restrict__ qout, __half* __restrict__ kout,
              const float* __restrict__ qw, const float* __restrict__ qb,
              const float* __restrict__ kw, const float* __restrict__ kb,
              const float* __restrict__ fcos, const float* __restrict__ fsin)
{
    const int warp = threadIdx.x >> 5, lane = threadIdx.x & 31;
    const int row  = blockIdx.x * 4 + warp;
    if (row >= BT_) return;

    const bool isQ = (blockIdx.y == 0);
    const float* buf = isQ ? qbuf : kbuf;
    __half* outh     = isQ ? qout : kout;
    const float* w   = isQ ? qw : kw;
    const float* bvec= isQ ? qb : kb;
    const float oscale = isQ ? QSCALE : 1.0f;

    const float4* in4 = reinterpret_cast<const float4*>(buf + (size_t)row * C_);
    float4 v[6];
    float sum = 0.f, sq = 0.f;
    #pragma unroll
    for (int i = 0; i < 6; i++) {
        v[i] = in4[lane + 32 * i];
        sum += v[i].x + v[i].y + v[i].z + v[i].w;
        sq  += v[i].x * v[i].x + v[i].y * v[i].y + v[i].z * v[i].z + v[i].w * v[i].w;
    }
    #pragma unroll
    for (int o = 16; o > 0; o >>= 1) {
        sum += __shfl_xor_sync(0xffffffffu, sum, o);
        sq  += __shfl_xor_sync(0xffffffffu, sq,  o);
    }
    const float mn = sum / (float)C_;
    const float rs = rsqrtf(sq / (float)C_ - mn * mn + 1e-5f);

    const int t = row % T_;
    const bool rope = (t >= OFFSET_);
    const int p = t - OFFSET_;

    const float4* w4 = reinterpret_cast<const float4*>(w);
    const float4* b4 = reinterpret_cast<const float4*>(bvec);
    uint2* out2 = reinterpret_cast<uint2*>(outh + (size_t)row * C_);

    #pragma unroll
    for (int i = 0; i < 6; i++) {
        const int f = lane + 32 * i;
        const float4 wv = w4[f], bv = b4[f];
        float e0 = (v[i].x - mn) * rs * wv.x + bv.x;
        float o0 = (v[i].y - mn) * rs * wv.y + bv.y;
        float e1 = (v[i].z - mn) * rs * wv.z + bv.z;
        float o1 = (v[i].w - mn) * rs * wv.w + bv.w;
        if (rope) {
            const int pr0 = (2 * f) & 31, pr1 = (2 * f + 1) & 31;
            const float c0 = fcos[p * 32 + pr0], s0 = fsin[p * 32 + pr0];
            const float c1 = fcos[p * 32 + pr1], s1 = fsin[p * 32 + pr1];
            float ne0 = e0 * c0 - o0 * s0, no0 = e0 * s0 + o0 * c0;
            float ne1 = e1 * c1 - o1 * s1, no1 = e1 * s1 + o1 * c1;
            e0 = ne0; o0 = no0; e1 = ne1; o1 = no1;
        }
        uint2 pk;
        pk.x = packh2(e0 * oscale, o0 * oscale);
        pk.y = packh2(e1 * oscale, o1 * oscale);
        out2[f] = pk;
    }
}

// ============================================================
// Flash attention: 3-stage cp.async K/V pipeline, 1 sync/iter.
// smem: Q (9216 B) then 3 stages of [K(9216) V(9216)].
// ============================================================
#define F_QB   9216u
#define F_STB  18432u
#define F_SMEM (F_QB + 3 * F_STB)   // 64512

__global__ __launch_bounds__(128)
void flash_mma(const __half* __restrict__ Qh, const __half* __restrict__ Kh,
               const __half* __restrict__ Vh, __half* __restrict__ Yh)
{
    extern __shared__ char smem[];
    const uint32_t sB = smem_u32(smem);

    const int tid  = threadIdx.x, lane = tid & 31, wid = tid >> 5;
    const int qb   = blockIdx.x * 64;
    const int bh   = blockIdx.y;
    const int b    = bh / H_, h = bh % H_;
    const size_t base = (size_t)b * T_ * C_ + h * HD_;
    const __half* Qg = Qh + base;
    const __half* Kg = Kh + base;
    const __half* Vg = Vh + base;
    __half*       Yg = Yh + base;

    const int cr  = tid >> 1;
    const int ccb = (tid & 1) * 32;

    auto copy_kv = [&](int kb, int st) {
        const uint32_t kDst = sB + F_QB + st * F_STB + (cr * 72 + ccb) * 2;
        const uint32_t vDst = kDst + 9216u;
        const __half* kSrc = Kg + (size_t)(kb + cr) * C_ + ccb;
        const __half* vSrc = Vg + (size_t)(kb + cr) * C_ + ccb;
        const bool ok = (kb + cr) < T_;
        cpa16(kDst,      kSrc,      ok);
        cpa16(kDst + 16, kSrc + 8,  ok);
        cpa16(kDst + 32, kSrc + 16, ok);
        cpa16(kDst + 48, kSrc + 24, ok);
        cpa16(vDst,      vSrc,      ok);
        cpa16(vDst + 16, vSrc + 8,  ok);
        cpa16(vDst + 32, vSrc + 16, ok);
        cpa16(vDst + 48, vSrc + 24, ok);
    };

    const int nKT = (T_ + 63) / 64;   // 17
    // prologue: Q + KV0 (group), KV1 (group)
    {
        const uint32_t qDst = sB + (cr * 72 + ccb) * 2;
        const __half* qSrc = Qg + (size_t)(qb + cr) * C_ + ccb;
        const bool ok = (qb + cr) < T_;
        cpa16(qDst,      qSrc,      ok);
        cpa16(qDst + 16, qSrc + 8,  ok);
        cpa16(qDst + 32, qSrc + 16, ok);
        cpa16(qDst + 48, qSrc + 24, ok);
        copy_kv(0, 0);
        CP_COMMIT();
        copy_kv(64, 1);
        CP_COMMIT();
    }

    const int gg = lane >> 3, lr = lane & 7;
    const int mbase = wid * 16;
    uint32_t qf[4][4];

    float m[2] = { -1e30f, -1e30f };
    float l[2] = { 0.f, 0.f };
    float o[8][4];
    #pragma unroll
    for (int nt = 0; nt < 8; nt++)
        #pragma unroll
        for (int r = 0; r < 4; r++) o[nt][r] = 0.f;

    int cur = 0;
    for (int kbi = 0; kbi < nKT; kbi++) {
        const int kb = kbi * 64;
        CP_WAIT(1);
        __syncthreads();

        if (kbi == 0) {
            #pragma unroll
            for (int kt = 0; kt < 4; kt++) {
                const uint32_t addr = sB +
                    ((mbase + (gg & 1) * 8 + lr) * 72 + kt * 16 + (gg >> 1) * 8) * 2;
                ldsm_x4(qf[kt], addr);
            }
        }

        const uint32_t kBase = sB + F_QB + cur * F_STB;
        const uint32_t vBase = kBase + 9216u;

        float s[8][4];
        #pragma unroll
        for (int nt = 0; nt < 8; nt++)
            #pragma unroll
            for (int r = 0; r < 4; r++) s[nt][r] = 0.f;

        #pragma unroll
        for (int np = 0; np < 4; np++) {
            #pragma unroll
            for (int kt = 0; kt < 4; kt++) {
                uint32_t r4[4];
                const uint32_t addr = kBase +
                    ((np * 16 + (gg >> 1) * 8 + lr) * 72 + kt * 16 + (gg & 1) * 8) * 2;
                ldsm_x4(r4, addr);
                mma16816(s[2 * np],     qf[kt], r4[0], r4[1]);
                mma16816(s[2 * np + 1], qf[kt], r4[2], r4[3]);
            }
        }

        if (kb + 64 > T_) {
            #pragma unroll
            for (int nt = 0; nt < 8; nt++) {
                const int c0 = kb + nt * 8 + (lane & 3) * 2;
                if (c0 >= T_)     { s[nt][0] = -1e30f; s[nt][2] = -1e30f; }
                if (c0 + 1 >= T_) { s[nt][1] = -1e30f; s[nt][3] = -1e30f; }
            }
        }

        float mx0 = -1e30f, mx1 = -1e30f;
        #pragma unroll
        for (int nt = 0; nt < 8; nt++) {
            mx0 = fmaxf(mx0, fmaxf(s[nt][0], s[nt][1]));
            mx1 = fmaxf(mx1, fmaxf(s[nt][2], s[nt][3]));
        }
        mx0 = fmaxf(mx0, __shfl_xor_sync(0xffffffffu, mx0, 1));
        mx0 = fmaxf(mx0, __shfl_xor_sync(0xffffffffu, mx0, 2));
        mx1 = fmaxf(mx1, __shfl_xor_sync(0xffffffffu, mx1, 1));
        mx1 = fmaxf(mx1, __shfl_xor_sync(0xffffffffu, mx1, 2));

        const float mn0 = fmaxf(m[0], mx0);
        const float mn1 = fmaxf(m[1], mx1);
        const float a0 = ex2(m[0] - mn0);
        const float a1 = ex2(m[1] - mn1);
        m[0] = mn0; m[1] = mn1;

        float sum0 = 0.f, sum1 = 0.f;
        #pragma unroll
        for (int nt = 0; nt < 8; nt++) {
            s[nt][0] = ex2(s[nt][0] - mn0);
            s[nt][1] = ex2(s[nt][1] - mn0);
            s[nt][2] = ex2(s[nt][2] - mn1);
            s[nt][3] = ex2(s[nt][3] - mn1);
            sum0 += s[nt][0] + s[nt][1];
            sum1 += s[nt][2] + s[nt][3];
        }
        sum0 += __shfl_xor_sync(0xffffffffu, sum0, 1);
        sum0 += __shfl_xor_sync(0xffffffffu, sum0, 2);
        sum1 += __shfl_xor_sync(0xffffffffu, sum1, 1);
        sum1 += __shfl_xor_sync(0xffffffffu, sum1, 2);
        l[0] = l[0] * a0 + sum0;
        l[1] = l[1] * a1 + sum1;

        #pragma unroll
        for (int nt = 0; nt < 8; nt++) {
            o[nt][0] *= a0; o[nt][1] *= a0;
            o[nt][2] *= a1; o[nt][3] *= a1;
        }

        #pragma unroll
        for (int kt = 0; kt < 4; kt++) {
            uint32_t pf[4];
            pf[0] = packh2(s[2 * kt][0],     s[2 * kt][1]);
            pf[1] = packh2(s[2 * kt][2],     s[2 * kt][3]);
            pf[2] = packh2(s[2 * kt + 1][0], s[2 * kt + 1][1]);
            pf[3] = packh2(s[2 * kt + 1][2], s[2 * kt + 1][3]);
            #pragma unroll
            for (int dp = 0; dp < 4; dp++) {
                uint32_t r4[4];
                const uint32_t addr = vBase +
                    ((kt * 16 + (gg & 1) * 8 + lr) * 72 + dp * 16 + (gg >> 1) * 8) * 2;
                ldsm_x4_t(r4, addr);
                mma16816(o[2 * dp],     pf, r4[0], r4[1]);
                mma16816(o[2 * dp + 1], pf, r4[2], r4[3]);
            }
        }

        if (kbi + 2 < nKT)
            copy_kv(kb + 128, (kbi + 2) % 3);
        CP_COMMIT();
        cur = (cur + 1) % 3;
    }

    const float inv0 = 1.0f / l[0];
    const float inv1 = 1.0f / l[1];
    const int r0 = qb + mbase + (lane >> 2);
    const int r1 = r0 + 8;
    #pragma unroll
    for (int nt = 0; nt < 8; nt++) {
        const int col = nt * 8 + (lane & 3) * 2;
        if (r0 < T_)
            *reinterpret_cast<__half2*>(Yg + (size_t)r0 * C_ + col) =
                __floats2half2_rn(o[nt][0] * inv0, o[nt][1] * inv0);
        if (r1 < T_)
            *reinterpret_cast<__half2*>(Yg + (size_t)r1 * C_ + col) =
                __floats2half2_rn(o[nt][2] * inv1, o[nt][3] * inv1);
    }
}

// ============================================================
// Host launcher
// ============================================================
extern "C" void kernel_launch(void* const* d_in, const int* in_sizes, int n_in,
                              void* d_out, int out_size)
{
    const float* x    = (const float*)d_in[0];
    const float* Wq   = (const float*)d_in[1];
    const float* Wk   = (const float*)d_in[2];
    const float* Wv   = (const float*)d_in[3];
    const float* Wp   = (const float*)d_in[4];
    const float* qn_w = (const float*)d_in[5];
    const float* qn_b = (const float*)d_in[6];
    const float* kn_w = (const float*)d_in[7];
    const float* kn_b = (const float*)d_in[8];
    const float* fcos = (const float*)d_in[9];
    const float* fsin = (const float*)d_in[10];
    float* out = (float*)d_out;

    float  *q, *k;
    __half *qh, *kh, *vh, *yh, *xh, *wqh, *wkh, *wvh, *wph;
    cudaGetSymbolAddress((void**)&q,   g_q);
    cudaGetSymbolAddress((void**)&k,   g_k);
    cudaGetSymbolAddress((void**)&qh,  g_qh);
    cudaGetSymbolAddress((void**)&kh,  g_kh);
    cudaGetSymbolAddress((void**)&vh,  g_vh);
    cudaGetSymbolAddress((void**)&yh,  g_yh);
    cudaGetSymbolAddress((void**)&xh,  g_xh);
    cudaGetSymbolAddress((void**)&wqh, g_wqh);
    cudaGetSymbolAddress((void**)&wkh, g_wkh);
    cudaGetSymbolAddress((void**)&wvh, g_wvh);
    cudaGetSymbolAddress((void**)&wph, g_wph);

    cudaFuncSetAttribute(qkv_gemm,  cudaFuncAttributeMaxDynamicSharedMemorySize, G_SMEM);
    cudaFuncSetAttribute(proj_gemm, cudaFuncAttributeMaxDynamicSharedMemorySize, G_SMEM);
    cudaFuncSetAttribute(flash_mma, cudaFuncAttributeMaxDynamicSharedMemorySize, F_SMEM);

    const int nx4 = (BT_ * C_) / 4;
    const int nw4 = (C_ * C_) / 4;
    f2h_kernel<<<(nx4 + 255) / 256, 256>>>(x, xh, nx4);
    f2h_w4<<<dim3((nw4 + 255) / 256, 4), 256>>>(Wq, Wk, Wv, Wp,
                                                wqh, wkh, wvh, wph, nw4);

    qkv_gemm<<<dim3(18, (BT_ + 127) / 128), 256, G_SMEM>>>(xh, wqh, wkh, wvh,
                                                           q, k, vh, BT_);

    const int lgrid = (BT_ + 3) / 4;
    ln_rope2<<<dim3(lgrid, 2), 128>>>(q, k, qh, kh, qn_w, qn_b, kn_w, kn_b,
                                      fcos, fsin);

    const dim3 fgrid((T_ + 63) / 64, B_ * H_);       // (17, 192)
    flash_mma<<<fgrid, 128, F_SMEM>>>(qh, kh, vh, yh);

    proj_gemm<<<dim3(6, (BT_ + 127) / 128), 256, G_SMEM>>>(yh, wph, out, BT_);
}